// round 17
// baseline (speedup 1.0000x reference)
#include <cuda_runtime.h>
#include <cuda_fp16.h>
#include <mma.h>
#include <cstdint>

using namespace nvcuda;

// ---------------------------------------------------------------------------
// GCN: 4 conv layers + global max pool + MLP.
// R17 = resubmit of R16 (container infra failure; source audited, unchanged).
// R16 = R15 (309.2us) + gather fused INTO GEMM staging for layers 3/4:
// k_fgg gathers (d2*t[dst] + sum nm*t[src]) directly to smem with bias+relu,
// then wmma. Deletes k_gather<96>/<64> and two h-buffer round-trips.
// ---------------------------------------------------------------------------

constexpr int NN = 100000;
constexpr int EE = 1600000;
constexpr int GG = 64;

__device__ __align__(16) float g_deg[NN];            // deg, then dis (in place)
__device__ __align__(16) int   g_src[EE];
__device__ __align__(16) int   g_dst[EE];
__device__ __align__(16) int   g_rank[EE];           // per-edge slot within dst
__device__ __align__(16) int2  g_cpack[EE];          // CSR by dst: (src, norm bits)
__device__ __align__(16) int   g_off[NN + 1];
__device__ __align__(16) int   g_cnt[NN];
__device__ __align__(16) int   g_aux[128];
__device__ __align__(16) float g_ax[NN];
__device__ __align__(16) __half g_A[(size_t)NN * 128];
__device__ __align__(16) __half g_B[(size_t)NN * 128];
__device__ __align__(16) __half g_C[(size_t)NN * 128];
__device__ __align__(16) float g_pool[GG * 32];
__device__ int g_is64;

struct __align__(8) h4 { __half2 a, b; };   // 4 halves, one 8B access

__device__ __forceinline__ float4 h4_to_f4(h4 v) {
    float2 f0 = __half22float2(v.a);
    float2 f1 = __half22float2(v.b);
    return make_float4(f0.x, f0.y, f1.x, f1.y);
}
__device__ __forceinline__ h4 f4_to_h4(float4 v) {
    h4 r;
    r.a = __floats2half2_rn(v.x, v.y);
    r.b = __floats2half2_rn(v.z, v.w);
    return r;
}
__device__ __forceinline__ void red_add_f32(float* p, float v) {
    asm volatile("red.global.add.f32 [%0], %1;" :: "l"(p), "f"(v) : "memory");
}
__device__ __forceinline__ void fma4(float4& a, float m, float4 v) {
    a.x = fmaf(m, v.x, a.x); a.y = fmaf(m, v.y, a.y);
    a.z = fmaf(m, v.z, a.z); a.w = fmaf(m, v.w, a.w);
}

// gather one (dst, 4-feature chunk): d2*t[dst] + sum nm*t[src], 4-wide unroll
template <int FO>
__device__ __forceinline__ float4 gather_chunk(const __half* __restrict__ t,
                                               int dst, size_t co) {
    const int r0 = g_off[dst], r1 = g_off[dst + 1];
    float d = g_deg[dst];
    float d2 = d * d;
    float4 a = h4_to_f4(*reinterpret_cast<const h4*>(t + (size_t)dst * FO + co));
    a.x *= d2; a.y *= d2; a.z *= d2; a.w *= d2;
    int j = r0;
    for (; j + 3 < r1; j += 4) {
        int2 p0 = g_cpack[j], p1 = g_cpack[j + 1];
        int2 p2 = g_cpack[j + 2], p3 = g_cpack[j + 3];
        float4 v0 = h4_to_f4(*reinterpret_cast<const h4*>(t + (size_t)p0.x * FO + co));
        float4 v1 = h4_to_f4(*reinterpret_cast<const h4*>(t + (size_t)p1.x * FO + co));
        float4 v2 = h4_to_f4(*reinterpret_cast<const h4*>(t + (size_t)p2.x * FO + co));
        float4 v3 = h4_to_f4(*reinterpret_cast<const h4*>(t + (size_t)p3.x * FO + co));
        fma4(a, __int_as_float(p0.y), v0);
        fma4(a, __int_as_float(p1.y), v1);
        fma4(a, __int_as_float(p2.y), v2);
        fma4(a, __int_as_float(p3.y), v3);
    }
    for (; j < r1; j++) {
        int2 p0 = g_cpack[j];
        float4 v0 = h4_to_f4(*reinterpret_cast<const h4*>(t + (size_t)p0.x * FO + co));
        fma4(a, __int_as_float(p0.y), v0);
    }
    return a;
}

// ---------------- init + dtype detect ----------------
// int64 node ids < 2^31 => every odd 32-bit word is 0. int32 => random ids.
__global__ void k_init_detect(const int* __restrict__ raw, int n) {
    int i = blockIdx.x * blockDim.x + threadIdx.x;
    if (i < n) {
        g_deg[i] = 1.0f;   // self loop weight
        g_cnt[i] = 0;
    }
    if (blockIdx.x == 0) {
        __shared__ int any;
        if (threadIdx.x == 0) any = 0;
        __syncthreads();
        int v = 0;
        for (int k = threadIdx.x; k < 2048; k += blockDim.x) v |= raw[2 * k + 1];
        if (v) atomicOr(&any, 1);
        __syncthreads();
        if (threadIdx.x == 0) g_is64 = (any == 0) ? 1 : 0;
    }
}

__global__ void k_edges_pre(const void* __restrict__ ei,
                            const float* __restrict__ w, int e) {
    int i = blockIdx.x * blockDim.x + threadIdx.x;
    if (i >= e) return;
    int s, d;
    if (g_is64) {
        const long long* p = (const long long*)ei;
        s = (int)p[i];
        d = (int)p[(size_t)e + i];
    } else {
        const int* p = (const int*)ei;
        s = p[i];
        d = p[e + i];
    }
    g_src[i] = s;
    g_dst[i] = d;
    atomicAdd(&g_deg[d], w[i]);
    g_rank[i] = atomicAdd(&g_cnt[d], 1);   // keep the rank
}

// ---------------- scan of g_cnt -> g_off ----------------

__global__ void k_scan1(int n) {   // 1024 threads/block, chunk=1024
    __shared__ int s[1024];
    int t = threadIdx.x;
    int base = blockIdx.x * 1024;
    int v = (base + t < n) ? g_cnt[base + t] : 0;
    s[t] = v;
    __syncthreads();
    for (int d = 1; d < 1024; d <<= 1) {
        int x = (t >= d) ? s[t - d] : 0;
        __syncthreads();
        s[t] += x;
        __syncthreads();
    }
    if (base + t < n) g_off[base + t + 1] = s[t];
    if (t == 1023) g_aux[blockIdx.x] = s[1023];
}

__global__ void k_scan2(int naux) {  // single block
    __shared__ int s[1024];
    int t = threadIdx.x;
    s[t] = (t < naux) ? g_aux[t] : 0;
    __syncthreads();
    for (int d = 1; d < 1024; d <<= 1) {
        int x = (t >= d) ? s[t - d] : 0;
        __syncthreads();
        s[t] += x;
        __syncthreads();
    }
    if (t < naux) g_aux[t] = (t > 0) ? s[t - 1] : 0;
}

// scan fixup + dis + ax self-term + pool zero
__global__ void k_scan3_dis(const float* __restrict__ x, int n) {
    int i = blockIdx.x * blockDim.x + threadIdx.x;
    if (i < GG * 32) g_pool[i] = 0.f;
    if (i >= n) return;
    g_off[i + 1] += g_aux[i >> 10];
    if (i == 0) g_off[0] = 0;
    float dg = g_deg[i];
    float dis = (dg > 0.f) ? rsqrtf(dg) : 0.f;
    g_deg[i] = dis;
    g_ax[i] = dis * dis * x[i];   // self-loop term; edges added in norm_fill
}

// norm + CSR fill (atomic-free slot via rank) + fused layer-1 Ax (red.add)
__global__ void k_norm_fill(const float* __restrict__ w,
                            const float* __restrict__ x, int e) {
    int i = blockIdx.x * blockDim.x + threadIdx.x;
    if (i >= e) return;
    int s = g_src[i];
    int d = g_dst[i];
    float nm = g_deg[s] * w[i] * g_deg[d];
    int pos = g_off[d] + g_rank[i];
    g_cpack[pos] = make_int2(s, __float_as_int(nm));
    red_add_f32(&g_ax[d], nm * x[s]);
}

// ---------------- wmma GEMM core (shared epilogue) ----------------
// Block: 128 threads = 4 warps; 64 rows x FO per block.
// As: [64][AP] fp16 staged (bias+relu applied). Wsh: [FI][FO] fp16.

template <int FI, int FO>
__device__ __forceinline__ void gemm_mma_core(
    const __half* As, int AP, const __half* Wsh, float* Cs,
    __half* __restrict__ tbuf, int n0, int n, int wid, int lane) {
    wmma::fragment<wmma::accumulator, 16, 16, 16, float> cfrag[FO / 16];
#pragma unroll
    for (int t = 0; t < FO / 16; t++) wmma::fill_fragment(cfrag[t], 0.f);

#pragma unroll
    for (int ks = 0; ks < FI / 16; ks++) {
        wmma::fragment<wmma::matrix_a, 16, 16, 16, __half, wmma::row_major> afrag;
        wmma::load_matrix_sync(afrag, As + (wid * 16) * AP + ks * 16, AP);
#pragma unroll
        for (int t = 0; t < FO / 16; t++) {
            wmma::fragment<wmma::matrix_b, 16, 16, 16, __half, wmma::row_major> bfrag;
            wmma::load_matrix_sync(bfrag, Wsh + (ks * 16) * FO + t * 16, FO);
            wmma::mma_sync(cfrag[t], afrag, bfrag, cfrag[t]);
        }
    }

    float* myCs = Cs + wid * 256;
    const int r = lane >> 1;
    const int c0 = (lane & 1) * 8;
    const int gn = n0 + wid * 16 + r;
#pragma unroll
    for (int t = 0; t < FO / 16; t++) {
        wmma::store_matrix_sync(myCs, cfrag[t], 16, wmma::mem_row_major);
        __syncwarp();
        if (gn < n) {
            float4 v0 = *reinterpret_cast<const float4*>(myCs + r * 16 + c0);
            float4 v1 = *reinterpret_cast<const float4*>(myCs + r * 16 + c0 + 4);
            h4* dst = reinterpret_cast<h4*>(tbuf + (size_t)gn * FO + t * 16 + c0);
            dst[0] = f4_to_h4(v0);
            dst[1] = f4_to_h4(v1);
        }
        __syncwarp();
    }
}

// ---------------- layer 2 GEMM (fused layer-1 expand): FI=128, FO=96 --------
// h1[node][k] = relu(ax[node]*W1[k] + b1[k]) staged to smem fp16.

__global__ __launch_bounds__(128)
void k_gemm2_mma(const float* __restrict__ W1, const float* __restrict__ b1,
                 const float* __restrict__ W2,
                 __half* __restrict__ tbuf, int n) {
    constexpr int FI = 128, FO = 96, AP = FI + 8;
    __shared__ __align__(32) __half As[64 * AP];
    __shared__ __align__(32) __half Wsh[FI * FO];
    __shared__ __align__(32) float Cs[4 * 256];
    __shared__ __align__(16) float W1s[FI], b1s[FI], axs[64];
    const int tid = threadIdx.x;
    const int wid = tid >> 5, lane = tid & 31;
    const int n0 = blockIdx.x * 64;

    W1s[tid] = W1[tid];
    b1s[tid] = b1[tid];
    if (tid < 64) {
        int nd = n0 + tid;
        axs[tid] = (nd < n) ? g_ax[nd] : 0.f;
    }
    for (int i = tid; i < FI * FO; i += 128) Wsh[i] = __float2half_rn(W2[i]);
    __syncthreads();

    // stage h1: thread owns node = tid&63, k = (tid>>6) + 2m
    {
        int node = tid & 63;
        float ax = axs[node];
        __half* row = As + node * AP;
#pragma unroll 8
        for (int m = 0; m < 64; m++) {
            int k = (tid >> 6) + 2 * m;
            row[k] = __float2half_rn(fmaxf(fmaf(ax, W1s[k], b1s[k]), 0.f));
        }
    }
    __syncthreads();

    gemm_mma_core<FI, FO>(As, AP, Wsh, Cs, tbuf, n0, n, wid, lane);
}

// ---------------- fused gather+GEMM layers 3,4 -------------------------------
// Stages As[node][k] = relu(gather(t_in, node)[k] + bias[k]) where
// gather = d2*t[dst] + sum nm*t[src]  (the GCN propagation), then wmma @ W.

template <int FI, int FO>
__global__ __launch_bounds__(128)
void k_fgg(const __half* __restrict__ tin, const float* __restrict__ bin,
           const float* __restrict__ W,
           __half* __restrict__ tbuf, int n) {
    constexpr int AP = FI + 8;
    constexpr int FI4 = FI / 4;
    __shared__ __align__(32) __half As[64 * AP];
    __shared__ __align__(32) __half Wsh[FI * FO];
    __shared__ __align__(32) float Cs[4 * 256];
    __shared__ __align__(16) float bs[FI];
    const int tid = threadIdx.x;
    const int wid = tid >> 5, lane = tid & 31;
    const int n0 = blockIdx.x * 64;

    for (int i = tid; i < FI; i += 128) bs[i] = bin[i];
    for (int i = tid; i < FI * FO; i += 128) Wsh[i] = __float2half_rn(W[i]);
    __syncthreads();

    for (int i = tid; i < 64 * FI4; i += 128) {
        int node = i / FI4, c = i % FI4;
        int gn = n0 + node;
        float4 v = make_float4(0.f, 0.f, 0.f, 0.f);
        if (gn < n) {
            float4 a = gather_chunk<FI>(tin, gn, (size_t)c * 4);
            v.x = fmaxf(a.x + bs[c * 4 + 0], 0.f);
            v.y = fmaxf(a.y + bs[c * 4 + 1], 0.f);
            v.z = fmaxf(a.z + bs[c * 4 + 2], 0.f);
            v.w = fmaxf(a.w + bs[c * 4 + 3], 0.f);
        }
        *reinterpret_cast<h4*>(As + node * AP + c * 4) = f4_to_h4(v);
    }
    __syncthreads();

    gemm_mma_core<FI, FO>(As, AP, Wsh, Cs, tbuf, n0, n, wid, lane);
}

// ---------------- layer-4 gather fused with pooling (FO=32) ----------------
// Thread = (dst, 4-feature chunk), 8 chunks/dst, 32 dsts/block.

__global__ __launch_bounds__(256)
void k_gather_pool(const __half* __restrict__ t, const float* __restrict__ b4,
                   const void* __restrict__ batch, int n) {
    __shared__ int smax[2][32];
    const int tid = threadIdx.x;
    if (tid < 64) smax[tid >> 5][tid & 31] = 0;
    __syncthreads();

    const int idx = blockIdx.x * 256 + tid;
    const int dst = idx >> 3;
    const int c = idx & 7;
    const int node0 = (blockIdx.x * 256) >> 3;   // block's first node
    const int is64 = g_is64;
    const long long* b64 = (const long long*)batch;
    const int* b32 = (const int*)batch;
    const int gmin = (node0 < n) ? (is64 ? (int)b64[node0] : b32[node0]) : 0;

    if (dst < n) {
        float4 a = gather_chunk<32>(t, dst, (size_t)c * 4);
        const int f0 = c * 4;
        float r0f = fmaxf(a.x + __ldg(&b4[f0 + 0]), 0.f);
        float r1f = fmaxf(a.y + __ldg(&b4[f0 + 1]), 0.f);
        float r2f = fmaxf(a.z + __ldg(&b4[f0 + 2]), 0.f);
        float r3f = fmaxf(a.w + __ldg(&b4[f0 + 3]), 0.f);
        // graph-local reduction (values >= 0 -> int compare valid)
        int g = is64 ? (int)b64[dst] : b32[dst];
        int l = g - gmin;
        if (l <= 1) {
            atomicMax(&smax[l][f0 + 0], __float_as_int(r0f));
            atomicMax(&smax[l][f0 + 1], __float_as_int(r1f));
            atomicMax(&smax[l][f0 + 2], __float_as_int(r2f));
            atomicMax(&smax[l][f0 + 3], __float_as_int(r3f));
        } else {  // safety net (cannot happen with graph size >> 32)
            atomicMax(reinterpret_cast<int*>(&g_pool[g * 32 + f0 + 0]), __float_as_int(r0f));
            atomicMax(reinterpret_cast<int*>(&g_pool[g * 32 + f0 + 1]), __float_as_int(r1f));
            atomicMax(reinterpret_cast<int*>(&g_pool[g * 32 + f0 + 2]), __float_as_int(r2f));
            atomicMax(reinterpret_cast<int*>(&g_pool[g * 32 + f0 + 3]), __float_as_int(r3f));
        }
    }
    __syncthreads();
    if (tid < 64) {
        int l = tid >> 5, f = tid & 31;
        int v = smax[l][f];
        int gg = gmin + l;
        if (v != 0 && gg < GG)
            atomicMax(reinterpret_cast<int*>(&g_pool[gg * 32 + f]), v);
    }
}

// ---------------- final MLP: relu(g@W5+b5)@W6+b6 ----------------

__global__ void k_mlp(const float* __restrict__ W5, const float* __restrict__ b5,
                      const float* __restrict__ W6, const float* __restrict__ b6,
                      float* __restrict__ out) {
    __shared__ float W5s[32 * 32], b5s[32], W6s[64], b6s[2];
    int t = threadIdx.x;   // 64 threads = 64 graphs
    for (int i = t; i < 1024; i += 64) W5s[i] = W5[i];
    if (t < 32) b5s[t] = b5[t];
    W6s[t] = W6[t];
    if (t < 2) b6s[t] = b6[t];
    __syncthreads();
    float p[32];
#pragma unroll
    for (int k = 0; k < 32; k++) p[k] = g_pool[t * 32 + k];
    float o0 = b6s[0], o1 = b6s[1];
#pragma unroll 4
    for (int j = 0; j < 32; j++) {
        float s = b5s[j];
#pragma unroll
        for (int k = 0; k < 32; k++) s = fmaf(p[k], W5s[k * 32 + j], s);
        s = fmaxf(s, 0.f);
        o0 = fmaf(s, W6s[j * 2], o0);
        o1 = fmaf(s, W6s[j * 2 + 1], o1);
    }
    out[t * 2] = o0;
    out[t * 2 + 1] = o1;
}

// ---------------- launch ----------------

extern "C" void kernel_launch(void* const* d_in, const int* in_sizes, int n_in,
                              void* d_out, int out_size) {
    const float* x  = (const float*)d_in[0];
    const void*  ei = d_in[1];
    const float* ew = (const float*)d_in[2];
    const void*  bt = d_in[3];
    const float* W1 = (const float*)d_in[4];
    const float* b1 = (const float*)d_in[5];
    const float* W2 = (const float*)d_in[6];
    const float* b2 = (const float*)d_in[7];
    const float* W3 = (const float*)d_in[8];
    const float* b3 = (const float*)d_in[9];
    const float* W4 = (const float*)d_in[10];
    const float* b4 = (const float*)d_in[11];
    const float* W5 = (const float*)d_in[12];
    const float* b5 = (const float*)d_in[13];
    const float* W6 = (const float*)d_in[14];
    const float* b6 = (const float*)d_in[15];
    float* out = (float*)d_out;

    const int n = in_sizes[0];
    const int e = in_sizes[2];

    const int nb  = (n + 255) / 256;
    const int ebk = (e + 255) / 256;
    const int nchunks = (n + 1023) / 1024;

    k_init_detect<<<nb, 256>>>((const int*)ei, n);
    k_edges_pre<<<ebk, 256>>>(ei, ew, e);
    k_scan1<<<nchunks, 1024>>>(n);
    k_scan2<<<1, 1024>>>(nchunks);
    k_scan3_dis<<<nb, 256>>>(x, n);
    k_norm_fill<<<ebk, 256>>>(ew, x, e);

    const int gx = (n + 63) / 64;

    __half* A; __half* B; __half* C;
    cudaGetSymbolAddress((void**)&A, g_A);
    cudaGetSymbolAddress((void**)&B, g_B);
    cudaGetSymbolAddress((void**)&C, g_C);

    // layer 2 (fused layer-1 expand): t2 -> B
    k_gemm2_mma<<<gx, 128>>>(W1, b1, W2, B, n);
    // layer 3: gather(B)+b2+relu @ W3 -> A     (fused gather+GEMM)
    k_fgg<96, 64><<<gx, 128>>>(B, b2, W3, A, n);
    // layer 4: gather(A)+b3+relu @ W4 -> C     (fused gather+GEMM)
    k_fgg<64, 32><<<gx, 128>>>(A, b3, W4, C, n);
    // final propagation + bias + relu + global max pool
    k_gather_pool<<<(n * 8 + 255) / 256, 256>>>(C, b4, bt, n);

    // MLP
    k_mlp<<<1, 64>>>(W5, b5, W6, b6, out);
}